// round 16
// baseline (speedup 1.0000x reference)
#include <cuda_runtime.h>
#include <cuda_fp16.h>
#include <stdint.h>
#include <math.h>

#define B_SZ    32
#define T_STEPS 128
#define I_CH    16
#define N_DIM   512

// ---------------- scratch ----------------
// W image (fp16): 128 blobs (i*8+kt) x 256KB; blob = 8 chunks (c = 64-n group) x 32KB.
// Fragment unit address: blob + c*32768 + ks*8192 + q*1024 + u*512 + lane*16  (+ (g&1)*8 half)
__device__ __align__(128) uint8_t g_wimg[128 * 262144];
// h fragments, double-buffered by step parity: [i][buf][hi 32KB | lo 32KB]
__device__ __align__(128) uint8_t g_hfrag[16 * 2 * 65536];
// per-producer flags, (i*8+kt)*32 (128B apart); flag = t+1 after step t's fragments published
__device__ unsigned int g_flag[128 * 32];

struct Params {
    const float* x;
    const float* U[4];
    const float* W[4];
    const float* bias[4];
    float* out;
};

// ---------------- helpers ----------------
__device__ __forceinline__ void mma16816(float* d, uint32_t a0, uint32_t a1, uint32_t a2,
                                         uint32_t a3, uint32_t b0, uint32_t b1) {
    asm volatile(
        "mma.sync.aligned.m16n8k16.row.col.f32.f16.f16.f32 "
        "{%0,%1,%2,%3}, {%4,%5,%6,%7}, {%8,%9}, {%0,%1,%2,%3};"
        : "+f"(d[0]), "+f"(d[1]), "+f"(d[2]), "+f"(d[3])
        : "r"(a0), "r"(a1), "r"(a2), "r"(a3), "r"(b0), "r"(b1));
}
__device__ __forceinline__ uint32_t packh(float x, float y) {
    __half hx = __float2half_rn(x), hy = __float2half_rn(y);
    return (uint32_t)__half_as_ushort(hx) | ((uint32_t)__half_as_ushort(hy) << 16);
}

// ---------------- prep: transpose + fp16-pack W; zero h-frag buf0 + flags ----------------
__global__ __launch_bounds__(256) void prep_kernel(Params p) {
    __shared__ float ts[128 * 68];     // [n 128][ko 64 + pad]
    int blob = blockIdx.x;             // 0..127
    int i = blob >> 3, kt = blob & 7;
    if (threadIdx.x == 0) g_flag[blob * 32] = 0;
    int m0 = kt * 64;
    uint8_t* dst = g_wimg + (size_t)blob * 262144;
    int tid = threadIdx.x;

    // zero this producer's chunk region in buf0 (read at t=0): hi 4KB + lo 4KB
    {
        uint4* zh = reinterpret_cast<uint4*>(g_hfrag + (size_t)(i * 2) * 65536 + kt * 4096);
        uint4* zl = reinterpret_cast<uint4*>(g_hfrag + (size_t)(i * 2) * 65536 + 32768 + kt * 4096);
        if (tid < 256) { zh[tid] = make_uint4(0, 0, 0, 0); zl[tid] = make_uint4(0, 0, 0, 0); }
    }

    for (int g = 0; g < 4; ++g) {
        const float* W = p.W[g] + (size_t)i * N_DIM * N_DIM;
        for (int nb = 0; nb < 4; ++nb) {            // 128-n groups
            __syncthreads();
            #pragma unroll
            for (int o = 0; o < 8; ++o) {
                int e = o * 256 + tid;              // 2048 float4 = 128 n x 16
                int row = e >> 4, qq = e & 15;
                float4 v = *reinterpret_cast<const float4*>(
                    W + (size_t)(nb * 128 + row) * N_DIM + m0 + qq * 4);
                float* sp = ts + row * 68 + qq * 4;
                sp[0] = v.x; sp[1] = v.y; sp[2] = v.z; sp[3] = v.w;
            }
            __syncthreads();
            #pragma unroll
            for (int o = 0; o < 8; ++o) {
                int idx = o * 256 + tid;            // 2048 fragment-halves per (g, nb)
                int cl  = idx >> 10;                // local 64-n chunk 0..1
                int r   = idx & 1023;
                int ks  = r >> 8;                   // 0..3
                int q   = (r >> 5) & 7;             // 0..7
                int lane = r & 31;
                int gid = lane >> 2, tig = lane & 3;
                int ko  = q * 8 + gid;              // 0..63
                int n0  = cl * 64 + ks * 16 + tig * 2;
                uint2 u;
                u.x = packh(ts[n0 * 68 + ko],       ts[(n0 + 1) * 68 + ko]);
                u.y = packh(ts[(n0 + 8) * 68 + ko], ts[(n0 + 9) * 68 + ko]);
                int chunk = nb * 2 + cl;
                int uu = g >> 1;
                uint32_t off = (uint32_t)(chunk * 32768 + ks * 8192 + q * 1024
                                          + uu * 512 + lane * 16 + (g & 1) * 8);
                *reinterpret_cast<uint2*>(dst + off) = u;
            }
        }
    }
}

// ---------------- persistent kernel ----------------
// dyn SMEM: A_hi @0 (32K) | A_lo @32768 (32K). A unit (16B) at ((it*2+bh)*32 + lane)*16
#define SM_A_LO 32768
#define SM_TOT  65536

__global__ __launch_bounds__(512, 1) void persist_kernel(Params p) {
    const int kt = blockIdx.x;   // 0..7 (64-wide k_out tile)
    const int i  = blockIdx.y;   // 0..15
    extern __shared__ __align__(16) uint8_t sm[];
    const uint8_t* blob = g_wimg + (size_t)(i * 8 + kt) * 262144;
    const int tid = threadIdx.x;

    const int lane = tid & 31, w = tid >> 5;
    const int bh = w & 1, q = w >> 1;           // q = 8-col group 0..7
    const int gid = lane >> 2, tig = lane & 3;

    const uint8_t* wq = blob + q * 1024 + lane * 16;

    // epilogue ownership: batches {b0, b0+8}, cols {kg0, kg0+1}
    const int b0  = bh * 16 + gid;
    const int kg0 = kt * 64 + q * 8 + tig * 2;

    // producer fragment address (chunk kt region)
    const int ks2 = (4 * q + tig) >> 3;
    const uint32_t a16b = (uint32_t)(((((kt * 4 + ks2) * 2 + bh) * 32 + gid * 4 + tig) * 16)
                                     + (q & 1) * 8);
    const size_t hf_base = (size_t)(i * 2) * 65536;

    float Uv[4][2], Bv[4][2];
    #pragma unroll
    for (int g = 0; g < 4; ++g) {
        Uv[g][0] = p.U[g][i * N_DIM + kg0];     Uv[g][1] = p.U[g][i * N_DIM + kg0 + 1];
        Bv[g][0] = p.bias[g][i * N_DIM + kg0];  Bv[g][1] = p.bias[g][i * N_DIM + kg0 + 1];
    }
    float creg[4] = {0.f, 0.f, 0.f, 0.f};
    float hreg[4] = {0.f, 0.f, 0.f, 0.f};
    float xc0 = __ldg(&p.x[((size_t)b0 * T_STEPS) * I_CH + i]);
    float xc1 = __ldg(&p.x[((size_t)(b0 + 8) * T_STEPS) * I_CH + i]);

    // staging role (per thread, fixed): hi/lo half and offset
    const int st_half = tid >> 8;               // 0 = hi, 1 = lo
    const int st_off  = (tid & 255) * 16;

    // prime 4-slot B pipeline with chunk kt (phase 0)
    uint4 Bp[4][2];
    #pragma unroll
    for (int ks = 0; ks < 4; ++ks) {
        const uint8_t* qp = wq + kt * 32768 + ks * 8192;
        Bp[ks][0] = __ldg(reinterpret_cast<const uint4*>(qp));
        Bp[ks][1] = __ldg(reinterpret_cast<const uint4*>(qp + 512));
    }

    volatile unsigned int* myflag = &g_flag[(i * 8 + kt) * 32];

    for (int t = 0; t < T_STEPS; ++t) {
        const uint8_t* hf_rd = g_hfrag + hf_base + (size_t)(t & 1) * 65536;

        float d[4][4];
        #pragma unroll
        for (int a = 0; a < 4; ++a)
            #pragma unroll
            for (int b = 0; b < 4; ++b) d[a][b] = 0.0f;

        for (int j = 0; j < 8; ++j) {
            const int c  = (kt + j) & 7;
            const int cn = (c + 1) & 7;

            // wait for producer (i, c) to publish step t-1 fragments
            if (t > 0 && j > 0) {
                if (tid == 0) {
                    unsigned v;
                    const unsigned int* fl = &g_flag[(i * 8 + c) * 32];
                    while (true) {
                        asm volatile("ld.acquire.gpu.u32 %0, [%1];"
                                     : "=r"(v) : "l"(fl) : "memory");
                        if (v >= (unsigned)t) break;
                        __nanosleep(64);
                    }
                }
                __syncthreads();
            }

            // stage chunk c (hi 4KB + lo 4KB)
            {
                uint4 v = __ldcg(reinterpret_cast<const uint4*>(
                    hf_rd + st_half * 32768 + c * 4096 + st_off));
                *reinterpret_cast<uint4*>(sm + st_half * 32768 + c * 4096 + st_off) = v;
            }
            __syncthreads();

            #pragma unroll
            for (int ks = 0; ks < 4; ++ks) {
                uint4 U0 = Bp[ks][0], U1 = Bp[ks][1];
                {   // prefetch next chunk's (cn) B fragments into slot ks
                    const uint8_t* qp = wq + cn * 32768 + ks * 8192;
                    Bp[ks][0] = __ldg(reinterpret_cast<const uint4*>(qp));
                    Bp[ks][1] = __ldg(reinterpret_cast<const uint4*>(qp + 512));
                }
                const int it = c * 4 + ks;
                uint32_t ab = (uint32_t)(((it * 2 + bh) * 32 + lane) * 16);
                uint4 Ah = *reinterpret_cast<const uint4*>(sm + ab);
                uint4 Al = *reinterpret_cast<const uint4*>(sm + SM_A_LO + ab);
                mma16816(d[0], Ah.x, Ah.y, Ah.z, Ah.w, U0.x, U0.y);
                mma16816(d[0], Al.x, Al.y, Al.z, Al.w, U0.x, U0.y);
                mma16816(d[1], Ah.x, Ah.y, Ah.z, Ah.w, U0.z, U0.w);
                mma16816(d[1], Al.x, Al.y, Al.z, Al.w, U0.z, U0.w);
                mma16816(d[2], Ah.x, Ah.y, Ah.z, Ah.w, U1.x, U1.y);
                mma16816(d[2], Al.x, Al.y, Al.z, Al.w, U1.x, U1.y);
                mma16816(d[3], Ah.x, Ah.y, Ah.z, Ah.w, U1.z, U1.w);
                mma16816(d[3], Al.x, Al.y, Al.z, Al.w, U1.z, U1.w);
            }
        }

        // prefetch next-step x
        float xn0 = 0.f, xn1 = 0.f;
        if (t + 1 < T_STEPS) {
            xn0 = __ldg(&p.x[((size_t)b0 * T_STEPS + t + 1) * I_CH + i]);
            xn1 = __ldg(&p.x[((size_t)(b0 + 8) * T_STEPS + t + 1) * I_CH + i]);
        }

        // ---- register-resident pointwise epilogue ----
        const float DT = 0.01f;
        const float A_OUT = 0.9900498337491681f;
        const float OMA_OUT = 0.009950166250831947f;
        #pragma unroll
        for (int rb = 0; rb < 2; ++rb) {
            int b = b0 + rb * 8;
            float xb = rb ? xc1 : xc0;
            float2 hv;
            #pragma unroll
            for (int rc = 0; rc < 2; ++rc) {
                int e = rb * 2 + rc;
                float pj = d[0][e] + xb * Uv[0][rc] + Bv[0][rc];
                float pi = d[1][e] + xb * Uv[1][rc] + Bv[1][rc];
                float pf = d[2][e] + xb * Uv[2][rc] + Bv[2][rc];
                float po = d[3][e] + xb * Uv[3][rc] + Bv[3][rc];

                float j  = tanhf(pj);
                float ig = 1.0f / (1.0f + expf(-pi));
                float fg = 1.0f / (1.0f + expf(-pf));
                float og = 1.0f / (1.0f + expf(-po));

                float h_old = hreg[e];
                float xm = -7.8125e-5f * j;
                float alpha_m = 1.0f + xm + 0.5f * xm * xm;
                float xr = -1.5625e-4f * ig;
                float ro = 1.0f + xr + 0.5f * xr * xr;
                float b_ad = ro * 0.1f + (1.0f - ro) * ig;
                float Bth  = 0.04f + 1.8f * b_ad;
                float mem  = j * alpha_m + (1.0f - alpha_m) * h_old - Bth * ig * DT;
                float spike = (mem - Bth) > 0.0f ? 1.0f : 0.0f;
                float mem_out = mem * A_OUT + OMA_OUT * spike + 0.08f;

                float c_new = creg[e] * fg + ig * spike * mem_out;
                creg[e] = c_new;
                float h_new = og * tanhf(c_new);
                hreg[e] = h_new;
                if (rc == 0) hv.x = h_new; else hv.y = h_new;
            }
            *reinterpret_cast<float2*>(
                p.out + (((size_t)b * T_STEPS + t) * I_CH + i) * N_DIM + kg0) = hv;
            if (t == T_STEPS - 1) {
                float* h_fin = p.out + (size_t)B_SZ * T_STEPS * I_CH * N_DIM;
                float* c_fin = h_fin + B_SZ * I_CH * N_DIM;
                size_t fidx = ((size_t)b * I_CH + i) * N_DIM + kg0;
                *reinterpret_cast<float2*>(h_fin + fidx) = hv;
                *reinterpret_cast<float2*>(c_fin + fidx) =
                    make_float2(creg[rb * 2], creg[rb * 2 + 1]);
            }
        }
        xc0 = xn0; xc1 = xn1;

        // ---- publish fragments for step t+1 ----
        if (t + 1 < T_STEPS) {
            uint8_t* hf_wr = g_hfrag + hf_base + (size_t)((t + 1) & 1) * 65536;
            __half h00 = __float2half_rn(hreg[0]), h01 = __float2half_rn(hreg[1]);
            __half h20 = __float2half_rn(hreg[2]), h21 = __float2half_rn(hreg[3]);
            uint32_t hv0 = (uint32_t)__half_as_ushort(h00) |
                           ((uint32_t)__half_as_ushort(h01) << 16);
            uint32_t hv8 = (uint32_t)__half_as_ushort(h20) |
                           ((uint32_t)__half_as_ushort(h21) << 16);
            uint32_t lv0 = packh(hreg[0] - __half2float(h00), hreg[1] - __half2float(h01));
            uint32_t lv8 = packh(hreg[2] - __half2float(h20), hreg[3] - __half2float(h21));
            __stcg(reinterpret_cast<uint2*>(hf_wr + a16b),         make_uint2(hv0, hv8));
            __stcg(reinterpret_cast<uint2*>(hf_wr + 32768 + a16b), make_uint2(lv0, lv8));
            __threadfence();
            __syncthreads();
            if (tid == 0) {
                unsigned fv = (unsigned)(t + 1);
                asm volatile("st.release.gpu.u32 [%0], %1;"
                             :: "l"((const unsigned int*)myflag), "r"(fv) : "memory");
            }
        }
    }
}

extern "C" void kernel_launch(void* const* d_in, const int* in_sizes, int n_in,
                              void* d_out, int out_size) {
    Params p;
    p.x = (const float*)d_in[0];
    for (int g = 0; g < 4; ++g) {
        p.U[g]    = (const float*)d_in[1 + g];
        p.W[g]    = (const float*)d_in[5 + g];
        p.bias[g] = (const float*)d_in[9 + g];
    }
    p.out = (float*)d_out;

    cudaFuncSetAttribute(persist_kernel, cudaFuncAttributeMaxDynamicSharedMemorySize, SM_TOT);

    prep_kernel<<<128, 256>>>(p);                 // packs W, zeroes h-frag buf0 + flags
    dim3 grid(8, I_CH);                           // 128 blocks, all co-resident
    persist_kernel<<<grid, 512, SM_TOT>>>(p);
}

// round 17
// speedup vs baseline: 1.1839x; 1.1839x over previous
#include <cuda_runtime.h>
#include <cuda_fp16.h>
#include <stdint.h>
#include <math.h>

#define B_SZ    32
#define T_STEPS 128
#define I_CH    16
#define N_DIM   512

// ---------------- scratch ----------------
// W image (fp16): 128 blobs (i*8+kt) x 256KB; blob = 8 chunks (c = 64-n group) x 32KB.
// Fragment unit address: blob + c*32768 + ks*8192 + q*1024 + u*512 + lane*16  (+ (g&1)*8 half)
__device__ __align__(128) uint8_t g_wimg[128 * 262144];
// h fragments (producer-packed, single fp16 plane): per channel 32KB, A-fragment layout.
__device__ __align__(128) uint8_t g_hfrag[16 * 32768];
__device__ unsigned int g_bar;

struct Params {
    const float* x;
    const float* U[4];
    const float* W[4];
    const float* bias[4];
    float* out;
};

// ---------------- helpers ----------------
__device__ __forceinline__ void mma16816(float* d, uint32_t a0, uint32_t a1, uint32_t a2,
                                         uint32_t a3, uint32_t b0, uint32_t b1) {
    asm volatile(
        "mma.sync.aligned.m16n8k16.row.col.f32.f16.f16.f32 "
        "{%0,%1,%2,%3}, {%4,%5,%6,%7}, {%8,%9}, {%0,%1,%2,%3};"
        : "+f"(d[0]), "+f"(d[1]), "+f"(d[2]), "+f"(d[3])
        : "r"(a0), "r"(a1), "r"(a2), "r"(a3), "r"(b0), "r"(b1));
}
__device__ __forceinline__ uint32_t packh(float x, float y) {
    __half hx = __float2half_rn(x), hy = __float2half_rn(y);
    return (uint32_t)__half_as_ushort(hx) | ((uint32_t)__half_as_ushort(hy) << 16);
}

// ---------------- prep: transpose + fp16-pack W; zero h-frag; reset barrier ----------------
__global__ __launch_bounds__(256) void prep_kernel(Params p) {
    __shared__ float ts[128 * 68];     // [n 128][ko 64 + pad]
    int blob = blockIdx.x;             // 0..127
    int i = blob >> 3, kt = blob & 7;
    if (blob == 0 && threadIdx.x == 0) g_bar = 0;
    int m0 = kt * 64;
    uint8_t* dst = g_wimg + (size_t)blob * 262144;
    int tid = threadIdx.x;

    // zero this blob's share of g_hfrag (512KB total / 128 blocks = 4KB)
    if (tid < 256) {
        uint4* z = reinterpret_cast<uint4*>(g_hfrag + (size_t)blob * 4096);
        z[tid] = make_uint4(0, 0, 0, 0);
    }

    for (int g = 0; g < 4; ++g) {
        const float* W = p.W[g] + (size_t)i * N_DIM * N_DIM;
        for (int nb = 0; nb < 4; ++nb) {            // 128-n groups
            __syncthreads();
            #pragma unroll
            for (int o = 0; o < 8; ++o) {
                int e = o * 256 + tid;              // 2048 float4 = 128 n x 16
                int row = e >> 4, qq = e & 15;
                float4 v = *reinterpret_cast<const float4*>(
                    W + (size_t)(nb * 128 + row) * N_DIM + m0 + qq * 4);
                float* sp = ts + row * 68 + qq * 4;
                sp[0] = v.x; sp[1] = v.y; sp[2] = v.z; sp[3] = v.w;
            }
            __syncthreads();
            #pragma unroll
            for (int o = 0; o < 8; ++o) {
                int idx = o * 256 + tid;            // 2048 fragment-halves per (g, nb)
                int cl  = idx >> 10;                // local 64-n chunk 0..1
                int r   = idx & 1023;
                int ks  = r >> 8;                   // 0..3
                int q   = (r >> 5) & 7;             // 0..7
                int lane = r & 31;
                int gid = lane >> 2, tig = lane & 3;
                int ko  = q * 8 + gid;              // 0..63
                int n0  = cl * 64 + ks * 16 + tig * 2;
                uint2 u;
                u.x = packh(ts[n0 * 68 + ko],       ts[(n0 + 1) * 68 + ko]);
                u.y = packh(ts[(n0 + 8) * 68 + ko], ts[(n0 + 9) * 68 + ko]);
                int chunk = nb * 2 + cl;
                int uu = g >> 1;
                uint32_t off = (uint32_t)(chunk * 32768 + ks * 8192 + q * 1024
                                          + uu * 512 + lane * 16 + (g & 1) * 8);
                *reinterpret_cast<uint2*>(dst + off) = u;
            }
        }
    }
}

// ---------------- persistent kernel ----------------
// dyn SMEM: A_hi @0 (32K). A unit (16B) at ((it*2+bh)*32 + lane)*16
#define SM_TOT  32768

__global__ __launch_bounds__(512, 1) void persist_kernel(Params p) {
    const int kt = blockIdx.x;   // 0..7 (64-wide k_out tile)
    const int i  = blockIdx.y;   // 0..15
    extern __shared__ __align__(16) uint8_t sm[];
    const uint8_t* blob = g_wimg + (size_t)(i * 8 + kt) * 262144;
    const int tid = threadIdx.x;

    const int lane = tid & 31, w = tid >> 5;
    const int bh = w & 1, q = w >> 1;           // q = 8-col group 0..7
    const int gid = lane >> 2, tig = lane & 3;

    const uint8_t* wq = blob + q * 1024 + lane * 16;

    // epilogue ownership (fixed over t): batches {b0, b0+8}, cols {kg0, kg0+1}
    const int b0  = bh * 16 + gid;
    const int kg0 = kt * 64 + q * 8 + tig * 2;

    // h-fragment scratch address this thread produces (both tops contiguous, 8B)
    uint8_t* hf_ch = g_hfrag + (size_t)i * 32768;
    const int ks2 = (4 * q + tig) >> 3;
    const uint32_t a16b = (uint32_t)(((((kt * 4 + ks2) * 2 + bh) * 32 + gid * 4 + tig) * 16)
                                     + (q & 1) * 8);

    float Uv[4][2], Bv[4][2];
    #pragma unroll
    for (int g = 0; g < 4; ++g) {
        Uv[g][0] = p.U[g][i * N_DIM + kg0];     Uv[g][1] = p.U[g][i * N_DIM + kg0 + 1];
        Bv[g][0] = p.bias[g][i * N_DIM + kg0];  Bv[g][1] = p.bias[g][i * N_DIM + kg0 + 1];
    }
    float creg[4] = {0.f, 0.f, 0.f, 0.f};
    float hreg[4] = {0.f, 0.f, 0.f, 0.f};
    float xc0 = __ldg(&p.x[((size_t)b0 * T_STEPS) * I_CH + i]);
    float xc1 = __ldg(&p.x[((size_t)(b0 + 8) * T_STEPS) * I_CH + i]);

    // prime 4-deep B pipeline (it = 0..3); wrap-around keeps it full across steps
    uint4 Bp[4][2];
    #pragma unroll
    for (int s = 0; s < 4; ++s) {
        const uint8_t* qp = wq + (s & 3) * 8192;   // c=0
        Bp[s][0] = __ldg(reinterpret_cast<const uint4*>(qp));
        Bp[s][1] = __ldg(reinterpret_cast<const uint4*>(qp + 512));
    }

    for (int t = 0; t < T_STEPS; ++t) {
        // ---- stage A: raw linear copy of producer-packed fragments (32KB) ----
        {
            const uint4* src = reinterpret_cast<const uint4*>(hf_ch);
            uint4* dst = reinterpret_cast<uint4*>(sm);
            #pragma unroll
            for (int o = 0; o < 4; ++o) {
                dst[o * 512 + tid] = __ldcg(&src[o * 512 + tid]);
            }
        }
        __syncthreads();

        // ---- mainloop: 32 flat (c,ks) iterations, 4-deep wrap-around B pipeline ----
        float d[4][4];
        #pragma unroll
        for (int a = 0; a < 4; ++a)
            #pragma unroll
            for (int b = 0; b < 4; ++b) d[a][b] = 0.0f;

        #pragma unroll
        for (int it = 0; it < 32; ++it) {
            const int sl = it & 3;
            uint4 U0 = Bp[sl][0], U1 = Bp[sl][1];
            {
                const int it2 = (it + 4) & 31;    // wraps to next step's head at tail
                const uint8_t* qp = wq + (it2 >> 2) * 32768 + (it2 & 3) * 8192;
                Bp[sl][0] = __ldg(reinterpret_cast<const uint4*>(qp));
                Bp[sl][1] = __ldg(reinterpret_cast<const uint4*>(qp + 512));
            }
            uint32_t ab = (uint32_t)(((it * 2 + bh) * 32 + lane) * 16);
            uint4 Ah = *reinterpret_cast<const uint4*>(sm + ab);
            mma16816(d[0], Ah.x, Ah.y, Ah.z, Ah.w, U0.x, U0.y);
            mma16816(d[1], Ah.x, Ah.y, Ah.z, Ah.w, U0.z, U0.w);
            mma16816(d[2], Ah.x, Ah.y, Ah.z, Ah.w, U1.x, U1.y);
            mma16816(d[3], Ah.x, Ah.y, Ah.z, Ah.w, U1.z, U1.w);
        }

        // prefetch next-step x (pre-barrier, independent)
        float xn0 = 0.f, xn1 = 0.f;
        if (t + 1 < T_STEPS) {
            xn0 = __ldg(&p.x[((size_t)b0 * T_STEPS + t + 1) * I_CH + i]);
            xn1 = __ldg(&p.x[((size_t)(b0 + 8) * T_STEPS + t + 1) * I_CH + i]);
        }

        // ---- register-resident pointwise epilogue ----
        const float DT = 0.01f;
        const float A_OUT = 0.9900498337491681f;
        const float OMA_OUT = 0.009950166250831947f;
        #pragma unroll
        for (int rb = 0; rb < 2; ++rb) {
            int b = b0 + rb * 8;
            float xb = rb ? xc1 : xc0;
            float2 hv;
            #pragma unroll
            for (int rc = 0; rc < 2; ++rc) {
                int e = rb * 2 + rc;
                float pj = d[0][e] + xb * Uv[0][rc] + Bv[0][rc];
                float pi = d[1][e] + xb * Uv[1][rc] + Bv[1][rc];
                float pf = d[2][e] + xb * Uv[2][rc] + Bv[2][rc];
                float po = d[3][e] + xb * Uv[3][rc] + Bv[3][rc];

                float j  = tanhf(pj);
                float ig = 1.0f / (1.0f + expf(-pi));
                float fg = 1.0f / (1.0f + expf(-pf));
                float og = 1.0f / (1.0f + expf(-po));

                float h_old = hreg[e];
                float xm = -7.8125e-5f * j;
                float alpha_m = 1.0f + xm + 0.5f * xm * xm;
                float xr = -1.5625e-4f * ig;
                float ro = 1.0f + xr + 0.5f * xr * xr;
                float b_ad = ro * 0.1f + (1.0f - ro) * ig;
                float Bth  = 0.04f + 1.8f * b_ad;
                float mem  = j * alpha_m + (1.0f - alpha_m) * h_old - Bth * ig * DT;
                float spike = (mem - Bth) > 0.0f ? 1.0f : 0.0f;
                float mem_out = mem * A_OUT + OMA_OUT * spike + 0.08f;

                float c_new = creg[e] * fg + ig * spike * mem_out;
                creg[e] = c_new;
                float h_new = og * tanhf(c_new);
                hreg[e] = h_new;
                if (rc == 0) hv.x = h_new; else hv.y = h_new;
            }
            *reinterpret_cast<float2*>(
                p.out + (((size_t)b * T_STEPS + t) * I_CH + i) * N_DIM + kg0) = hv;
            if (t == T_STEPS - 1) {
                float* h_fin = p.out + (size_t)B_SZ * T_STEPS * I_CH * N_DIM;
                float* c_fin = h_fin + B_SZ * I_CH * N_DIM;
                size_t fidx = ((size_t)b * I_CH + i) * N_DIM + kg0;
                *reinterpret_cast<float2*>(h_fin + fidx) = hv;
                *reinterpret_cast<float2*>(c_fin + fidx) =
                    make_float2(creg[rb * 2], creg[rb * 2 + 1]);
            }
        }
        xc0 = xn0; xc1 = xn1;

        // ---- producer-side fragment packing for next step (single fp16 plane) ----
        if (t + 1 < T_STEPS) {
            uint32_t hv0 = packh(hreg[0], hreg[1]);
            uint32_t hv8 = packh(hreg[2], hreg[3]);
            __stcg(reinterpret_cast<uint2*>(hf_ch + a16b), make_uint2(hv0, hv8));
        }

        // ---- grid barrier (128 CTAs, all co-resident) ----
        if (t + 1 < T_STEPS) {
            __threadfence();
            __syncthreads();
            if (tid == 0) {
                atomicAdd(&g_bar, 1u);
                unsigned target = (unsigned)(t + 1) * 128u;
                unsigned v;
                do {
                    asm volatile("ld.acquire.gpu.u32 %0, [%1];"
                                 : "=r"(v) : "l"(&g_bar) : "memory");
                } while (v < target);
            }
            __syncthreads();
        }
    }
}

extern "C" void kernel_launch(void* const* d_in, const int* in_sizes, int n_in,
                              void* d_out, int out_size) {
    Params p;
    p.x = (const float*)d_in[0];
    for (int g = 0; g < 4; ++g) {
        p.U[g]    = (const float*)d_in[1 + g];
        p.W[g]    = (const float*)d_in[5 + g];
        p.bias[g] = (const float*)d_in[9 + g];
    }
    p.out = (float*)d_out;

    cudaFuncSetAttribute(persist_kernel, cudaFuncAttributeMaxDynamicSharedMemorySize, SM_TOT);

    prep_kernel<<<128, 256>>>(p);                 // packs W, zeroes h-frag, resets g_bar
    dim3 grid(8, I_CH);                           // 128 blocks, all co-resident
    persist_kernel<<<grid, 512, SM_TOT>>>(p);
}